// round 17
// baseline (speedup 1.0000x reference)
#include <cuda_runtime.h>
#include <cuda_bf16.h>
#include <math.h>
#include <stdint.h>

#define NNODES 50000
#define NEDGES 800000
#define MT_PAD 3128          // ceil(50048/16): m16-tiles padded to CTA(128) multiple
#define KT_MAX 16            // K up to 256
#define SCAN_B 49            // ceil(50000/1024)

// ---------------- scratch (static device globals; no runtime allocation) ----
__device__ float g_xlr[(size_t)NNODES * 512];   // fused [xl | xr] gemm output
__device__ uint4 g_Ah[(size_t)MT_PAD * KT_MAX * 32];
__device__ uint4 g_Al[(size_t)MT_PAD * KT_MAX * 32];
// per-layer B operand buffers (hi/lo) so all packs can run up front
__device__ uint4 g_Bh1[32 * 8 * 32],  g_Bl1[32 * 8 * 32];
__device__ uint4 g_Bh2[32 * 16 * 32], g_Bl2[32 * 16 * 32];
__device__ uint4 g_Bh3[8 * 16 * 32],  g_Bl3[8 * 16 * 32];
__device__ uint4 g_Bhf[4 * 4 * 32],   g_Blf[4 * 4 * 32];
__device__ int   g_deg  [NNODES + 1];
__device__ int   g_rowp [NNODES + 1];
__device__ int   g_pos  [NNODES];
__device__ int   g_chain[SCAN_B];
__device__ int   g_flag [SCAN_B];
__device__ int   g_csrc [NEDGES];

// ======================= helpers ============================================
__device__ __forceinline__ uint32_t pack_bf16(float a, float b) { // a->low, b->high
    __nv_bfloat162 t;
    t.x = __float2bfloat16(a);
    t.y = __float2bfloat16(b);
    return *reinterpret_cast<uint32_t*>(&t);
}

__device__ __forceinline__ void mma16816(float* d, const uint4& a,
                                         uint32_t b0, uint32_t b1) {
    asm volatile(
        "mma.sync.aligned.m16n8k16.row.col.f32.bf16.bf16.f32 "
        "{%0,%1,%2,%3}, {%4,%5,%6,%7}, {%8,%9}, {%0,%1,%2,%3};"
        : "+f"(d[0]), "+f"(d[1]), "+f"(d[2]), "+f"(d[3])
        : "r"(a.x), "r"(a.y), "r"(a.z), "r"(a.w), "r"(b0), "r"(b1));
}

// ======================= device bodies ======================================
__device__ __forceinline__ void hist_dev(const int* __restrict__ dst,
                                         int* __restrict__ deg, int E, int gi) {
    if (gi < E) atomicAdd(&deg[dst[gi]], 1);
}

__device__ __forceinline__ void fillcsr_dev(const int* __restrict__ src,
                                            const int* __restrict__ dst,
                                            int* __restrict__ pos,
                                            int* __restrict__ csrc, int E, int gi) {
    if (gi < E) {
        int p = atomicAdd(&pos[dst[gi]], 1);
        csrc[p] = src[gi];
    }
}

__device__ __forceinline__ void splitA_dev(const float* __restrict__ A,
                                           uint4* __restrict__ Ah,
                                           uint4* __restrict__ Al,
                                           int M, int Kt, int gi) {
    int blk = gi >> 5, lane = gi & 31;
    int mt = blk / Kt, kt = blk - mt * Kt;
    if (mt >= MT_PAD) return;
    int g = lane >> 2, l = lane & 3;
    int K = Kt * 16;
    int r0 = mt * 16 + g, r1 = r0 + 8;
    int c0 = kt * 16 + 2 * l, c2 = c0 + 8;

    float2 v00 = make_float2(0.f, 0.f), v10 = v00, v02 = v00, v12 = v00;
    if (r0 < M) {
        v00 = *(const float2*)(A + (size_t)r0 * K + c0);
        v02 = *(const float2*)(A + (size_t)r0 * K + c2);
    }
    if (r1 < M) {
        v10 = *(const float2*)(A + (size_t)r1 * K + c0);
        v12 = *(const float2*)(A + (size_t)r1 * K + c2);
    }

    float h00x = __bfloat162float(__float2bfloat16(v00.x));
    float h00y = __bfloat162float(__float2bfloat16(v00.y));
    float h10x = __bfloat162float(__float2bfloat16(v10.x));
    float h10y = __bfloat162float(__float2bfloat16(v10.y));
    float h02x = __bfloat162float(__float2bfloat16(v02.x));
    float h02y = __bfloat162float(__float2bfloat16(v02.y));
    float h12x = __bfloat162float(__float2bfloat16(v12.x));
    float h12y = __bfloat162float(__float2bfloat16(v12.y));

    uint4 hi, lo;
    hi.x = pack_bf16(v00.x, v00.y);
    hi.y = pack_bf16(v10.x, v10.y);
    hi.z = pack_bf16(v02.x, v02.y);
    hi.w = pack_bf16(v12.x, v12.y);
    lo.x = pack_bf16(v00.x - h00x, v00.y - h00y);
    lo.y = pack_bf16(v10.x - h10x, v10.y - h10y);
    lo.z = pack_bf16(v02.x - h02x, v02.y - h02y);
    lo.w = pack_bf16(v12.x - h12x, v12.y - h12y);

    size_t off = (size_t)blk * 32 + lane;
    Ah[off] = hi;
    Al[off] = lo;
}

__device__ __forceinline__ void packB_dev(const float* __restrict__ Wl,
                                          const float* __restrict__ Wr,
                                          uint4* __restrict__ Bh,
                                          uint4* __restrict__ Bl,
                                          int Kt, int HC, int gi) {
    int blk = gi >> 5, lane = gi & 31;
    int nt16 = blk / Kt, kt = blk - nt16 * Kt;
    int N2 = 2 * HC;
    if (nt16 * 16 >= N2) return;
    int g = lane >> 2, l = lane & 3;
    int k0 = kt * 16 + 2 * l;

    uint4 hi, lo;
    uint32_t* hp = &hi.x;
    uint32_t* lp = &lo.x;
#pragma unroll
    for (int half = 0; half < 2; half++) {
        int col = nt16 * 16 + half * 8 + g;
        const float* Wt = (col < HC) ? Wl : Wr;
        int c = (col < HC) ? col : col - HC;
#pragma unroll
        for (int r = 0; r < 2; r++) {
            int k = k0 + r * 8;
            float a = Wt[(size_t)k * HC + c];
            float b = Wt[(size_t)(k + 1) * HC + c];
            float ha = __bfloat162float(__float2bfloat16(a));
            float hb = __bfloat162float(__float2bfloat16(b));
            hp[half * 2 + r] = pack_bf16(a, b);
            lp[half * 2 + r] = pack_bf16(a - ha, b - hb);
        }
    }
    size_t off = (size_t)blk * 32 + lane;
    Bh[off] = hi;
    Bl[off] = lo;
}

// ================= HMMA GEMM body (3-term bf16 split, R11 tile) =============
template <int Kt>
__device__ __forceinline__ void mma_body(
    int bx, int by,
    const uint4* __restrict__ Ah, const uint4* __restrict__ Al,
    const uint4* __restrict__ Bh, const uint4* __restrict__ Bl,
    float* __restrict__ C, const float* __restrict__ bias2, int M, int N2)
{
    const int tid = threadIdx.x;
    const int wid = tid >> 5, lane = tid & 31;
    const int g = lane >> 2, l = lane & 3;
    const int mw = wid & 3, nw = wid >> 2;      // 4 x 2 warp grid

    const int mt0  = by * 8 + mw * 2;   // 2 m16 tiles per warp
    const int nt0  = bx * 4 + nw * 2;   // 2 n16 tiles per warp

    float acc[2][4][4];
#pragma unroll
    for (int i = 0; i < 2; i++)
#pragma unroll
        for (int j = 0; j < 4; j++)
#pragma unroll
            for (int r = 0; r < 4; r++) acc[i][j][r] = 0.f;

    const uint4* pa0 = Ah + ((size_t)(mt0)     * Kt) * 32 + lane;
    const uint4* pa1 = Ah + ((size_t)(mt0 + 1) * Kt) * 32 + lane;
    const uint4* qa0 = Al + ((size_t)(mt0)     * Kt) * 32 + lane;
    const uint4* qa1 = Al + ((size_t)(mt0 + 1) * Kt) * 32 + lane;
    const uint4* pb0 = Bh + ((size_t)(nt0)     * Kt) * 32 + lane;
    const uint4* pb1 = Bh + ((size_t)(nt0 + 1) * Kt) * 32 + lane;
    const uint4* qb0 = Bl + ((size_t)(nt0)     * Kt) * 32 + lane;
    const uint4* qb1 = Bl + ((size_t)(nt0 + 1) * Kt) * 32 + lane;

    uint4 ah[2][2], al[2][2], bh[2][2], bl[2][2];
    ah[0][0] = pa0[0]; ah[0][1] = pa1[0];
    al[0][0] = qa0[0]; al[0][1] = qa1[0];
    bh[0][0] = pb0[0]; bh[0][1] = pb1[0];
    bl[0][0] = qb0[0]; bl[0][1] = qb1[0];

#pragma unroll
    for (int kt = 0; kt < Kt; kt++) {
        const int cur = kt & 1, nxt = cur ^ 1;
        if (kt + 1 < Kt) {
            ah[nxt][0] = pa0[(kt + 1) * 32]; ah[nxt][1] = pa1[(kt + 1) * 32];
            al[nxt][0] = qa0[(kt + 1) * 32]; al[nxt][1] = qa1[(kt + 1) * 32];
            bh[nxt][0] = pb0[(kt + 1) * 32]; bh[nxt][1] = pb1[(kt + 1) * 32];
            bl[nxt][0] = qb0[(kt + 1) * 32]; bl[nxt][1] = qb1[(kt + 1) * 32];
        }

        // term AhBh
#pragma unroll
        for (int i = 0; i < 2; i++)
#pragma unroll
            for (int j = 0; j < 2; j++) {
                mma16816(acc[i][2 * j],     ah[cur][i], bh[cur][j].x, bh[cur][j].y);
                mma16816(acc[i][2 * j + 1], ah[cur][i], bh[cur][j].z, bh[cur][j].w);
            }
        // term AhBl
#pragma unroll
        for (int i = 0; i < 2; i++)
#pragma unroll
            for (int j = 0; j < 2; j++) {
                mma16816(acc[i][2 * j],     ah[cur][i], bl[cur][j].x, bl[cur][j].y);
                mma16816(acc[i][2 * j + 1], ah[cur][i], bl[cur][j].z, bl[cur][j].w);
            }
        // term AlBh
#pragma unroll
        for (int i = 0; i < 2; i++)
#pragma unroll
            for (int j = 0; j < 2; j++) {
                mma16816(acc[i][2 * j],     al[cur][i], bh[cur][j].x, bh[cur][j].y);
                mma16816(acc[i][2 * j + 1], al[cur][i], bh[cur][j].z, bh[cur][j].w);
            }
    }

    // epilogue
#pragma unroll
    for (int i = 0; i < 2; i++) {
        int rbase = (mt0 + i) * 16;
#pragma unroll
        for (int j = 0; j < 4; j++) {
            int col = (nt0 + (j >> 1)) * 16 + (j & 1) * 8 + 2 * l;
            float b0 = 0.f, b1 = 0.f;
            if (bias2) { b0 = bias2[col]; b1 = bias2[col + 1]; }
            int r0 = rbase + g, r1 = rbase + g + 8;
            if (r0 < M)
                *(float2*)(C + (size_t)r0 * N2 + col) =
                    make_float2(acc[i][j][0] + b0, acc[i][j][1] + b1);
            if (r1 < M)
                *(float2*)(C + (size_t)r1 * N2 + col) =
                    make_float2(acc[i][j][2] + b0, acc[i][j][3] + b1);
        }
    }
}

// ======================= kernels ============================================
// zeroes deg AND the scan chain flags (replay determinism)
__global__ void zero_deg_kernel(int* __restrict__ deg, int* __restrict__ flag,
                                int n) {
    int i = blockIdx.x * blockDim.x + threadIdx.x;
    if (i <= n) deg[i] = 0;
    if (i < SCAN_B) flag[i] = 0;
}

// merged prep: splitA(L1) interleaved 1:1 with hist, then all 4 packBs.
__global__ void prep_kernel(
    const float* __restrict__ x,
    const float* __restrict__ Wl1, const float* __restrict__ Wr1,
    const float* __restrict__ Wl2, const float* __restrict__ Wr2,
    const float* __restrict__ Wl3, const float* __restrict__ Wr3,
    const float* __restrict__ Wlin,
    uint4* __restrict__ Ah, uint4* __restrict__ Al,
    uint4* __restrict__ Bh1, uint4* __restrict__ Bl1,
    uint4* __restrict__ Bh2, uint4* __restrict__ Bl2,
    uint4* __restrict__ Bh3, uint4* __restrict__ Bl3,
    uint4* __restrict__ Bhf, uint4* __restrict__ Blf,
    const int* __restrict__ dst, int* __restrict__ deg)
{
    int vb = blockIdx.x;
    int tid = threadIdx.x;
    if (vb < 6256) {                       // interleaved: even=splitA, odd=hist
        if (vb & 1) {
            int hb = vb >> 1;              // 0..3127
            if (hb < 3125) hist_dev(dst, deg, NEDGES, hb * 256 + tid);
        } else {
            splitA_dev(x, Ah, Al, NNODES, 8, (vb >> 1) * 256 + tid);
        }
        return;
    }
    vb -= 6256;
    if (vb < 32) { packB_dev(Wl1, Wr1, Bh1, Bl1, 8, 256, vb * 256 + tid); return; }
    vb -= 32;
    if (vb < 64) { packB_dev(Wl2, Wr2, Bh2, Bl2, 16, 256, vb * 256 + tid); return; }
    vb -= 64;
    if (vb < 16) { packB_dev(Wl3, Wr3, Bh3, Bl3, 16, 64, vb * 256 + tid); return; }
    vb -= 16;
    packB_dev(Wlin, Wlin, Bhf, Blf, 4, 64, vb * 256 + tid);   // 2 blocks
}
#define PREP_BLOCKS (6256 + 32 + 64 + 16 + 2)

// single-kernel chained exclusive scan (decoupled lookback, serial chain).
// 49 blocks, all co-resident -> spin is deadlock-free. flags pre-zeroed.
__global__ __launch_bounds__(1024) void scan_chain_kernel(
    const int* __restrict__ deg, int* __restrict__ rowp,
    int* __restrict__ pos, int* __restrict__ chain, int* __restrict__ flag,
    int n, int E)
{
    __shared__ int ws[32];
    __shared__ int s_prev;
    const int b = blockIdx.x;
    const int i = b * 1024 + threadIdx.x;
    const int lane = threadIdx.x & 31, w = threadIdx.x >> 5;

    int v = (i < n) ? deg[i] : 0;
    int x = v;
#pragma unroll
    for (int o = 1; o < 32; o <<= 1) {
        int t = __shfl_up_sync(0xffffffffu, x, o);
        if (lane >= o) x += t;
    }
    if (lane == 31) ws[w] = x;
    __syncthreads();
    if (w == 0) {
        int y = ws[lane];
#pragma unroll
        for (int o = 1; o < 32; o <<= 1) {
            int t = __shfl_up_sync(0xffffffffu, y, o);
            if (lane >= o) y += t;
        }
        ws[lane] = y;
    }
    __syncthreads();
    int excl  = x - v + (w ? ws[w - 1] : 0);
    int total = ws[31];

    if (threadIdx.x == 0) {
        int prev = 0;
        if (b > 0) {
            while (atomicAdd(&flag[b - 1], 0) == 0) {}
            __threadfence();
            prev = chain[b - 1];
        }
        chain[b] = prev + total;
        __threadfence();
        atomicExch(&flag[b], 1);
        s_prev = prev;
    }
    __syncthreads();

    int r = excl + s_prev;
    if (i < n) {
        rowp[i] = r;
        pos[i]  = r;
    }
    if (i == 0) rowp[n] = E;
}

// merged: mma<8> layer-1 GEMM interleaved 1:1 with fillcsr (independent)
__global__ __launch_bounds__(256, 2) void mma_fill_kernel(
    const uint4* __restrict__ Ah, const uint4* __restrict__ Al,
    const uint4* __restrict__ Bh, const uint4* __restrict__ Bl,
    float* __restrict__ C, int M, int N2,
    const int* __restrict__ src, const int* __restrict__ dst,
    int* __restrict__ pos, int* __restrict__ csrc)
{
    int vb = blockIdx.x;                   // grid = 6256
    if (vb & 1) {
        int fb = vb >> 1;                  // 0..3127
        if (fb < 3125)
            fillcsr_dev(src, dst, pos, csrc, NEDGES, fb * 256 + threadIdx.x);
        return;
    }
    int mb = vb >> 1;                      // 0..3127
    mma_body<8>(mb & 7, mb >> 3, Ah, Al, Bh, Bl, C, nullptr, M, N2);
}

template <int Kt>
__global__ __launch_bounds__(256, 2) void mma_gemm(
    const uint4* __restrict__ Ah, const uint4* __restrict__ Al,
    const uint4* __restrict__ Bh, const uint4* __restrict__ Bl,
    float* __restrict__ C, const float* __restrict__ bias2, int M, int N2)
{
    mma_body<Kt>(blockIdx.x, blockIdx.y, Ah, Al, Bh, Bl, C, bias2, M, N2);
}

// ============ shared node_agg math macros (proven R13 forms) ================
#define NA_LOAD_PL(dst, sidx, PLc) do { \
    const float* _p = xlr + (size_t)(sidx) * (W2c) + lane * (PLc); \
    if constexpr ((PLc) == 8) { \
        float4 _a = *(const float4*)(_p); \
        float4 _b = *(const float4*)(_p + 4); \
        dst[0]=_a.x; dst[1]=_a.y; dst[2]=_a.z; dst[3]=_a.w; \
        dst[4]=_b.x; dst[5]=_b.y; dst[6]=_b.z; dst[7]=_b.w; \
    } else { \
        float2 _a = *(const float2*)(_p); \
        dst[0]=_a.x; dst[1]=_a.y; \
    } \
} while (0)

#define NA_SCORE(P, pl, PLc, LPHc) do { \
    P = 0.f; \
    _Pragma("unroll") \
    for (int _j = 0; _j < (PLc); _j++) { \
        float _v = pl[_j] + rxr[_j]; \
        _v = fmaxf(_v, 0.2f * _v); \
        P = fmaf(ratt[_j], _v, P); \
    } \
    _Pragma("unroll") \
    for (int _o = (LPHc) / 2; _o > 0; _o >>= 1) \
        P += __shfl_xor_sync(0xffffffffu, P, _o); \
} while (0)

#define NA_ONLINE(P, pl, PLc) do { \
    float _mn = fmaxf(m, P); \
    float _sc = __expf(m - _mn); \
    float _w  = __expf(P - _mn); \
    s = fmaf(s, _sc, _w); \
    _Pragma("unroll") \
    for (int _j = 0; _j < (PLc); _j++) \
        acc[_j] = fmaf(acc[_j], _sc, _w * pl[_j]); \
    m = _mn; \
} while (0)

// ======== node_agg for layers 1-2 (H=4, C=64, ELU) with frag output =========
__global__ __launch_bounds__(512) void node_agg_frag(
    const float* __restrict__ xlr, const int* __restrict__ rowp,
    const int* __restrict__ csrc, const float* __restrict__ att,
    const float* __restrict__ bias,
    uint4* __restrict__ Ah, uint4* __restrict__ Al, int n)
{
    constexpr int HC = 256, W2c = 512, PL = 8, LPH = 8;
    __shared__ float sv[16][260];   // padded stride to spread banks

    const int wid = threadIdx.x >> 5, lane = threadIdx.x & 31;
    const int mt = blockIdx.x;
    const int nid = mt * 16 + wid;

    if (nid < n) {
        int row = rowp[nid];
        int end = rowp[nid + 1];

        float rxr[PL], ratt[PL];
        {
            const float* xrp  = xlr + (size_t)nid * W2c + HC + lane * PL;
            const float* attp = att + lane * PL;
            float4 a = *(const float4*)(xrp);
            float4 b = *(const float4*)(xrp + 4);
            rxr[0]=a.x; rxr[1]=a.y; rxr[2]=a.z; rxr[3]=a.w;
            rxr[4]=b.x; rxr[5]=b.y; rxr[6]=b.z; rxr[7]=b.w;
            float4 c = *(const float4*)(attp);
            float4 d = *(const float4*)(attp + 4);
            ratt[0]=c.x; ratt[1]=c.y; ratt[2]=c.z; ratt[3]=c.w;
            ratt[4]=d.x; ratt[5]=d.y; ratt[6]=d.z; ratt[7]=d.w;
        }

        float m = -INFINITY, s = 0.f;
        float acc[PL];
#pragma unroll
        for (int j = 0; j < PL; j++) acc[j] = 0.f;

        int i = row;
        for (; i + 2 <= end; i += 2) {
            int s0 = csrc[i], s1 = csrc[i + 1];
            float pl0[PL], pl1[PL];
            NA_LOAD_PL(pl0, s0, PL);
            NA_LOAD_PL(pl1, s1, PL);
            float p0, p1;
            NA_SCORE(p0, pl0, PL, LPH);
            NA_SCORE(p1, pl1, PL, LPH);
            NA_ONLINE(p0, pl0, PL);
            NA_ONLINE(p1, pl1, PL);
        }
        if (i < end) {
            int s0 = csrc[i];
            float pl0[PL];
            NA_LOAD_PL(pl0, s0, PL);
            float p0;
            NA_SCORE(p0, pl0, PL, LPH);
            NA_ONLINE(p0, pl0, PL);
        }

        float inv = 1.f / (s + 1e-16f);
        const float* bp = bias + lane * PL;
        float v[PL];
#pragma unroll
        for (int j = 0; j < PL; j++) {
            float t = acc[j] * inv + bp[j];
            v[j] = t > 0.f ? t : expm1f(t);   // ELU
        }
        float* srow = sv[wid] + lane * PL;
        *(float4*)(srow)     = make_float4(v[0], v[1], v[2], v[3]);
        *(float4*)(srow + 4) = make_float4(v[4], v[5], v[6], v[7]);
    }
    __syncthreads();

    // fragment write: thread (kt = wid, lane) emits one hi + one lo uint4
    {
        const int kt = wid;
        const int g = lane >> 2, l = lane & 3;
        const int c0 = kt * 16 + 2 * l;
        float2 a0 = *(float2*)&sv[g][c0];
        float2 a1 = *(float2*)&sv[g + 8][c0];
        float2 a2 = *(float2*)&sv[g][c0 + 8];
        float2 a3 = *(float2*)&sv[g + 8][c0 + 8];

        uint4 hi, lo;
        hi.x = pack_bf16(a0.x, a0.y);
        hi.y = pack_bf16(a1.x, a1.y);
        hi.z = pack_bf16(a2.x, a2.y);
        hi.w = pack_bf16(a3.x, a3.y);
        lo.x = pack_bf16(a0.x - __bfloat162float(__float2bfloat16(a0.x)),
                         a0.y - __bfloat162float(__float2bfloat16(a0.y)));
        lo.y = pack_bf16(a1.x - __bfloat162float(__float2bfloat16(a1.x)),
                         a1.y - __bfloat162float(__float2bfloat16(a1.y)));
        lo.z = pack_bf16(a2.x - __bfloat162float(__float2bfloat16(a2.x)),
                         a2.y - __bfloat162float(__float2bfloat16(a2.y)));
        lo.w = pack_bf16(a3.x - __bfloat162float(__float2bfloat16(a3.x)),
                         a3.y - __bfloat162float(__float2bfloat16(a3.y)));

        size_t off = ((size_t)mt * 16 + kt) * 32 + lane;
        Ah[off] = hi;
        Al[off] = lo;
    }
}

// ======== node_agg layer 3 (H=1, C=64, no ELU) -> Kt=4 frag output ==========
__global__ __launch_bounds__(512) void node_agg_l3_frag(
    const float* __restrict__ xlr, const int* __restrict__ rowp,
    const int* __restrict__ csrc, const float* __restrict__ att,
    const float* __restrict__ bias,
    uint4* __restrict__ Ah, uint4* __restrict__ Al, int n)
{
    constexpr int HC = 64, W2c = 128, PL = 2, LPH = 32;
    __shared__ float sv[16][68];    // padded stride

    const int wid = threadIdx.x >> 5, lane = threadIdx.x & 31;
    const int mt = blockIdx.x;
    const int nid = mt * 16 + wid;

    if (nid < n) {
        int row = rowp[nid];
        int end = rowp[nid + 1];

        float rxr[PL], ratt[PL];
        {
            const float* xrp  = xlr + (size_t)nid * W2c + HC + lane * PL;
            float2 a = *(const float2*)(xrp);
            rxr[0] = a.x; rxr[1] = a.y;
            float2 c = *(const float2*)(att + lane * PL);
            ratt[0] = c.x; ratt[1] = c.y;
        }

        float m = -INFINITY, s = 0.f;
        float acc[PL] = {0.f, 0.f};

        int i = row;
        for (; i + 2 <= end; i += 2) {
            int s0 = csrc[i], s1 = csrc[i + 1];
            float pl0[PL], pl1[PL];
            NA_LOAD_PL(pl0, s0, PL);
            NA_LOAD_PL(pl1, s1, PL);
            float p0, p1;
            NA_SCORE(p0, pl0, PL, LPH);
            NA_SCORE(p1, pl1, PL, LPH);
            NA_ONLINE(p0, pl0, PL);
            NA_ONLINE(p1, pl1, PL);
        }
        if (i < end) {
            int s0 = csrc[i];
            float pl0[PL];
            NA_LOAD_PL(pl0, s0, PL);
            float p0;
            NA_SCORE(p0, pl0, PL, LPH);
            NA_ONLINE(p0, pl0, PL);
        }

        float inv = 1.f / (s + 1e-16f);
        float v0 = acc[0] * inv + bias[2 * lane];
        float v1 = acc[1] * inv + bias[2 * lane + 1];
        *(float2*)&sv[wid][2 * lane] = make_float2(v0, v1);
    }
    __syncthreads();

    // fragment write (Kt = 4): warps 0-3 -> kt; one hi + one lo uint4 each
    if (wid < 4) {
        const int kt = wid;
        const int g = lane >> 2, l = lane & 3;
        const int c0 = kt * 16 + 2 * l;
        float2 a0 = *(float2*)&sv[g][c0];
        float2 a1 = *(float2*)&sv[g + 8][c0];
        float2 a2 = *(float2*)&sv[g][c0 + 8];
        float2 a3 = *(float2*)&sv[g + 8][c0 + 8];

        uint4 hi, lo;
        hi.x = pack_bf16(a0.x, a0.y);
        hi.y = pack_bf16(a1.x, a1.y);
        hi.z = pack_bf16(a2.x, a2.y);
        hi.w = pack_bf16(a3.x, a3.y);
        lo.x = pack_bf16(a0.x - __bfloat162float(__float2bfloat16(a0.x)),
                         a0.y - __bfloat162float(__float2bfloat16(a0.y)));
        lo.y = pack_bf16(a1.x - __bfloat162float(__float2bfloat16(a1.x)),
                         a1.y - __bfloat162float(__float2bfloat16(a1.y)));
        lo.z = pack_bf16(a2.x - __bfloat162float(__float2bfloat16(a2.x)),
                         a2.y - __bfloat162float(__float2bfloat16(a2.y)));
        lo.w = pack_bf16(a3.x - __bfloat162float(__float2bfloat16(a3.x)),
                         a3.y - __bfloat162float(__float2bfloat16(a3.y)));

        size_t off = ((size_t)mt * 4 + kt) * 32 + lane;
        Ah[off] = hi;
        Al[off] = lo;
    }
}

// ======================= host driver =========================================
extern "C" void kernel_launch(void* const* d_in, const int* in_sizes, int n_in,
                              void* d_out, int out_size)
{
    const float* x    = (const float*)d_in[0];
    const float* Wl1  = (const float*)d_in[1];
    const float* Wr1  = (const float*)d_in[2];
    const float* att1 = (const float*)d_in[3];
    const float* b1   = (const float*)d_in[4];
    const float* Wl2  = (const float*)d_in[5];
    const float* Wr2  = (const float*)d_in[6];
    const float* att2 = (const float*)d_in[7];
    const float* b2   = (const float*)d_in[8];
    const float* Wl3  = (const float*)d_in[9];
    const float* Wr3  = (const float*)d_in[10];
    const float* att3 = (const float*)d_in[11];
    const float* b3   = (const float*)d_in[12];
    const float* Wlin = (const float*)d_in[13];
    const float* blin = (const float*)d_in[14];
    const int*   ei   = (const int*)d_in[15];

    const int* src = ei;
    const int* dst = ei + NEDGES;

    void* tp;
    float* xlr;
    uint4 *Ah, *Al, *Bh1, *Bl1, *Bh2, *Bl2, *Bh3, *Bl3, *Bhf, *Blf;
    int *deg, *rowp, *pos, *chain, *flag, *csrc;
    cudaGetSymbolAddress(&tp, g_xlr);   xlr   = (float*)tp;
    cudaGetSymbolAddress(&tp, g_Ah);    Ah    = (uint4*)tp;
    cudaGetSymbolAddress(&tp, g_Al);    Al    = (uint4*)tp;
    cudaGetSymbolAddress(&tp, g_Bh1);   Bh1   = (uint4*)tp;
    cudaGetSymbolAddress(&tp, g_Bl1);   Bl1   = (uint4*)tp;
    cudaGetSymbolAddress(&tp, g_Bh2);   Bh2   = (uint4*)tp;
    cudaGetSymbolAddress(&tp, g_Bl2);   Bl2   = (uint4*)tp;
    cudaGetSymbolAddress(&tp, g_Bh3);   Bh3   = (uint4*)tp;
    cudaGetSymbolAddress(&tp, g_Bl3);   Bl3   = (uint4*)tp;
    cudaGetSymbolAddress(&tp, g_Bhf);   Bhf   = (uint4*)tp;
    cudaGetSymbolAddress(&tp, g_Blf);   Blf   = (uint4*)tp;
    cudaGetSymbolAddress(&tp, g_deg);   deg   = (int*)tp;
    cudaGetSymbolAddress(&tp, g_rowp);  rowp  = (int*)tp;
    cudaGetSymbolAddress(&tp, g_pos);   pos   = (int*)tp;
    cudaGetSymbolAddress(&tp, g_chain); chain = (int*)tp;
    cudaGetSymbolAddress(&tp, g_flag);  flag  = (int*)tp;
    cudaGetSymbolAddress(&tp, g_csrc);  csrc  = (int*)tp;

    const int NB16 = (NNODES + 15) / 16;    // 3125 exact
    const int MTB  = (NNODES + 127) / 128;  // 391 CTA rows

    // 1: zero deg + scan flags (must precede prep's hist blocks)
    zero_deg_kernel<<<(NNODES + 256) / 256, 256>>>(deg, flag, NNODES);
    // 2: splitA(L1) || hist, then all packBs
    prep_kernel<<<PREP_BLOCKS, 256>>>(x, Wl1, Wr1, Wl2, Wr2, Wl3, Wr3, Wlin,
                                      Ah, Al, Bh1, Bl1, Bh2, Bl2, Bh3, Bl3,
                                      Bhf, Blf, dst, deg);
    // 3: single-kernel chained prefix scan
    scan_chain_kernel<<<SCAN_B, 1024>>>(deg, rowp, pos, chain, flag,
                                        NNODES, NEDGES);
    // 4: layer-1 GEMM || fillcsr
    mma_fill_kernel<<<6256, 256>>>(Ah, Al, Bh1, Bl1, xlr, NNODES, 512,
                                   src, dst, pos, csrc);
    // 5: layer-1 aggregation -> layer-2 A fragments
    node_agg_frag<<<NB16, 512>>>(xlr, rowp, csrc, att1, b1, Ah, Al, NNODES);
    // 6-7: layer 2
    mma_gemm<16><<<dim3(8, MTB), 256>>>(Ah, Al, Bh2, Bl2, xlr, nullptr,
                                        NNODES, 512);
    node_agg_frag<<<NB16, 512>>>(xlr, rowp, csrc, att2, b2, Ah, Al, NNODES);
    // 8-9: layer 3 (agg emits final-linear Kt=4 fragments)
    mma_gemm<16><<<dim3(2, MTB), 256>>>(Ah, Al, Bh3, Bl3, xlr, nullptr,
                                        NNODES, 128);
    node_agg_l3_frag<<<NB16, 512>>>(xlr, rowp, csrc, att3, b3, Ah, Al, NNODES);
    // 10: final linear via HMMA
    mma_gemm<4><<<dim3(1, MTB), 256>>>(Ah, Al, Bhf, Blf, (float*)d_out, blin,
                                       NNODES, 64);
}